// round 14
// baseline (speedup 1.0000x reference)
#include <cuda_runtime.h>
#include <cuda_bf16.h>
#include <cuda_fp16.h>
#include <math.h>

// ---------------- constants ----------------
#define Bc   2
#define Nc   512
#define CSc  384
#define CZc  128
#define Hc   12
#define CHc  32
#define PQc  4
#define PVc  8
#define HIDc 1536
#define BNc  (Bc*Nc)          // 1024
#define CATc 2304
#define PROJc 1728            // 1152 qkv | 144 qp | 144 kp | 288 vp

#define WLc  0.5773502691896258f
#define WCc  0.23570226039551587f
#define INV_SQRT_CH 0.17677669529663687f

// ---------------- f32x2 helpers ----------------
__device__ __forceinline__ unsigned long long pk2(float lo, float hi) {
    unsigned long long r; asm("mov.b64 %0, {%1, %2};" : "=l"(r) : "f"(lo), "f"(hi)); return r;
}
__device__ __forceinline__ void fma2(unsigned long long& c, unsigned long long a, unsigned long long b) {
    asm("fma.rn.f32x2 %0, %1, %2, %0;" : "+l"(c) : "l"(a), "l"(b));
}
__device__ __forceinline__ float2 upk2(unsigned long long v) {
    float2 r; asm("mov.b64 {%0, %1}, %2;" : "=f"(r.x), "=f"(r.y) : "l"(v)); return r;
}

// ---------------- scratch ----------------
__device__ float g_s0  [BNc*CSc];
__device__ float g_proj[BNc*PROJc];
__device__ float g_qn  [Bc*Hc*Nc];
__device__ float g_kn  [Bc*Hc*Nc];
__device__ float g_att [(size_t)Bc*Hc*Nc*Nc];
__device__ float g_cat [BNc*CATc];
__device__ float g_x   [BNc*CSc];
__device__ float g_hs  [BNc*HIDc];
__device__ float g_p0  [BNc*CSc];
__device__ float g_p1  [BNc*CSc];
__device__ float g_p2  [BNc*CSc];
__device__ float g_avp0[BNc*Hc*56];
__device__ float g_avp1[BNc*Hc*56];

// ---------------- rmsnorm ----------------
__global__ void k_rmsnorm(const float* __restrict__ in, const float* __restrict__ w,
                          float* __restrict__ out, int rows, int C) {
    int warp = (blockIdx.x*blockDim.x + threadIdx.x) >> 5;
    int lane = threadIdx.x & 31;
    if (warp >= rows) return;
    const float* x = in + (size_t)warp*C;
    float ss = 0.f;
    for (int c = lane; c < C; c += 32) { float v = x[c]; ss += v*v; }
    #pragma unroll
    for (int o = 16; o; o >>= 1) ss += __shfl_xor_sync(0xffffffffu, ss, o);
    float scale = rsqrtf(ss/(float)C + 1e-6f);
    float* y = out + (size_t)warp*C;
    for (int c = lane; c < C; c += 32) y[c] = x[c]*scale*w[c];
}

// ---------------- fused projection GEMM: BM=128 BN=64, 8x4 micro (f32x2) ----------------
__global__ __launch_bounds__(256) void k_proj(
        const float* __restrict__ A,
        const float* __restrict__ Wqkv, const float* __restrict__ Wqp,
        const float* __restrict__ Wkp,  const float* __restrict__ Wvp,
        float* __restrict__ P) {
    __shared__ float As[2][16][132];
    __shared__ float Ws[2][16][68];
    const int K = CSc;
    int tid = threadIdx.x;
    int bm = blockIdx.y*128, col0 = blockIdx.x*64;
    int ty = tid >> 4, tx = tid & 15;
    unsigned long long acc[4][4];
    #pragma unroll
    for (int i=0;i<4;i++) { acc[i][0]=0ull;acc[i][1]=0ull;acc[i][2]=0ull;acc[i][3]=0ull; }

    int r0 = tid >> 2, kf = tid & 3;
    int col = col0 + r0;
    const float* wrowp;
    if (col < 1152)      wrowp = Wqkv + (size_t)col*K;
    else if (col < 1296) wrowp = Wqp  + (size_t)(col-1152)*K;
    else if (col < 1440) wrowp = Wkp  + (size_t)(col-1296)*K;
    else                 wrowp = Wvp  + (size_t)(col-1440)*K;
    const float* a0p = A + (size_t)(bm+r0)*K;
    const float* a1p = A + (size_t)(bm+r0+64)*K;

    {
        float4 a0 = *(const float4*)&a0p[kf*4];
        float4 a1 = *(const float4*)&a1p[kf*4];
        float4 w0 = *(const float4*)&wrowp[kf*4];
        #pragma unroll
        for (int j=0;j<4;j++) {
            As[0][kf*4+j][r0]    = ((const float*)&a0)[j];
            As[0][kf*4+j][r0+64] = ((const float*)&a1)[j];
            Ws[0][kf*4+j][r0]    = ((const float*)&w0)[j];
        }
    }
    __syncthreads();

    int nT = K >> 4;
    for (int t0 = 0; t0 < nT; t0++) {
        int cur = t0 & 1;
        float4 pa0, pa1, pw0;
        bool nx = (t0+1 < nT);
        if (nx) {
            int k0 = (t0+1)*16;
            pa0 = *(const float4*)&a0p[k0 + kf*4];
            pa1 = *(const float4*)&a1p[k0 + kf*4];
            pw0 = *(const float4*)&wrowp[k0 + kf*4];
        }
        #pragma unroll
        for (int kk = 0; kk < 16; kk++) {
            float4 a4a = *(const float4*)&As[cur][kk][ty*8];
            float4 a4b = *(const float4*)&As[cur][kk][ty*8+4];
            float4 b4  = *(const float4*)&Ws[cur][kk][tx*4];
            unsigned long long a2[4] = {pk2(a4a.x,a4a.y), pk2(a4a.z,a4a.w),
                                        pk2(a4b.x,a4b.y), pk2(a4b.z,a4b.w)};
            unsigned long long bd[4] = {pk2(b4.x,b4.x), pk2(b4.y,b4.y),
                                        pk2(b4.z,b4.z), pk2(b4.w,b4.w)};
            #pragma unroll
            for (int i=0;i<4;i++)
                #pragma unroll
                for (int j=0;j<4;j++) fma2(acc[i][j], a2[i], bd[j]);
        }
        if (nx) {
            int nb = cur^1;
            #pragma unroll
            for (int j=0;j<4;j++) {
                As[nb][kf*4+j][r0]    = ((const float*)&pa0)[j];
                As[nb][kf*4+j][r0+64] = ((const float*)&pa1)[j];
                Ws[nb][kf*4+j][r0]    = ((const float*)&pw0)[j];
            }
        }
        __syncthreads();
    }
    #pragma unroll
    for (int i=0;i<4;i++) {
        int m = bm + ty*8 + 2*i;
        #pragma unroll
        for (int j=0;j<4;j++) {
            float2 v = upk2(acc[i][j]);
            P[(size_t)m*PROJc + col0 + tx*4 + j]     = v.x;
            P[(size_t)(m+1)*PROJc + col0 + tx*4 + j] = v.y;
        }
    }
}

// ---------------- split-K GEMM: BM=128 BN=64, 8x4 micro (f32x2) ----------------
__global__ __launch_bounds__(256) void k_gemmK(
        const float* __restrict__ A, const float* __restrict__ W,
        float* __restrict__ P0, float* __restrict__ P1, float* __restrict__ P2,
        int Nd, int K, int klen) {
    __shared__ float As[2][16][132];
    __shared__ float Ws[2][16][68];
    int tid = threadIdx.x;
    int bm = blockIdx.y*128, bn = blockIdx.x*64;
    int kofs = blockIdx.z * klen;
    float* P = (blockIdx.z == 0) ? P0 : (blockIdx.z == 1 ? P1 : P2);
    int ty = tid >> 4, tx = tid & 15;
    unsigned long long acc[4][4];
    #pragma unroll
    for (int i=0;i<4;i++) { acc[i][0]=0ull;acc[i][1]=0ull;acc[i][2]=0ull;acc[i][3]=0ull; }

    int r0 = tid >> 2, kf = tid & 3;
    const float* a0p = A + (size_t)(bm+r0)*K + kofs;
    const float* a1p = A + (size_t)(bm+r0+64)*K + kofs;
    const float* wp  = W + (size_t)(bn+r0)*K + kofs;

    {
        float4 a0 = *(const float4*)&a0p[kf*4];
        float4 a1 = *(const float4*)&a1p[kf*4];
        float4 w0 = *(const float4*)&wp[kf*4];
        #pragma unroll
        for (int j=0;j<4;j++) {
            As[0][kf*4+j][r0]    = ((const float*)&a0)[j];
            As[0][kf*4+j][r0+64] = ((const float*)&a1)[j];
            Ws[0][kf*4+j][r0]    = ((const float*)&w0)[j];
        }
    }
    __syncthreads();

    int nT = klen >> 4;
    for (int t0 = 0; t0 < nT; t0++) {
        int cur = t0 & 1;
        float4 pa0, pa1, pw0;
        bool nx = (t0+1 < nT);
        if (nx) {
            int k0 = (t0+1)*16;
            pa0 = *(const float4*)&a0p[k0 + kf*4];
            pa1 = *(const float4*)&a1p[k0 + kf*4];
            pw0 = *(const float4*)&wp[k0 + kf*4];
        }
        #pragma unroll
        for (int kk = 0; kk < 16; kk++) {
            float4 a4a = *(const float4*)&As[cur][kk][ty*8];
            float4 a4b = *(const float4*)&As[cur][kk][ty*8+4];
            float4 b4  = *(const float4*)&Ws[cur][kk][tx*4];
            unsigned long long a2[4] = {pk2(a4a.x,a4a.y), pk2(a4a.z,a4a.w),
                                        pk2(a4b.x,a4b.y), pk2(a4b.z,a4b.w)};
            unsigned long long bd[4] = {pk2(b4.x,b4.x), pk2(b4.y,b4.y),
                                        pk2(b4.z,b4.z), pk2(b4.w,b4.w)};
            #pragma unroll
            for (int i=0;i<4;i++)
                #pragma unroll
                for (int j=0;j<4;j++) fma2(acc[i][j], a2[i], bd[j]);
        }
        if (nx) {
            int nb = cur^1;
            #pragma unroll
            for (int j=0;j<4;j++) {
                As[nb][kf*4+j][r0]    = ((const float*)&pa0)[j];
                As[nb][kf*4+j][r0+64] = ((const float*)&pa1)[j];
                Ws[nb][kf*4+j][r0]    = ((const float*)&pw0)[j];
            }
        }
        __syncthreads();
    }
    #pragma unroll
    for (int i=0;i<4;i++) {
        int m = bm + ty*8 + 2*i;
        #pragma unroll
        for (int j=0;j<4;j++) {
            float2 v = upk2(acc[i][j]);
            P[(size_t)m*Nd + bn + tx*4 + j]     = v.x;
            P[(size_t)(m+1)*Nd + bn + tx*4 + j] = v.y;
        }
    }
}

__global__ void k_reduce3(const float* __restrict__ Cadd,
                          const float* __restrict__ p0, const float* __restrict__ p1,
                          const float* __restrict__ p2, float* __restrict__ out) {
    int i = (blockIdx.x*blockDim.x + threadIdx.x)*4;
    if (i >= BNc*CSc) return;
    float4 c = *(const float4*)&Cadd[i];
    float4 a = *(const float4*)&p0[i];
    float4 b = *(const float4*)&p1[i];
    float4 d = *(const float4*)&p2[i];
    float4 o;
    o.x = c.x + a.x + b.x + d.x;
    o.y = c.y + a.y + b.y + d.y;
    o.z = c.z + a.z + b.z + d.z;
    o.w = c.w + a.w + b.w + d.w;
    *(float4*)&out[i] = o;
}

// ---------------- GLU GEMM: BM=128 BN=64 (f32x2) ----------------
__global__ __launch_bounds__(256) void k_glu(
        const float* __restrict__ A, const float* __restrict__ W,
        float* __restrict__ HS, int K) {
    __shared__ float As[2][16][132];
    __shared__ float Ws[2][16][132];
    int tid = threadIdx.x;
    int bm = blockIdx.y*128, n0 = blockIdx.x*64;
    int ty = tid >> 4, tx = tid & 15;
    unsigned long long acc1[4][4], acc2[4][4];
    #pragma unroll
    for (int i=0;i<4;i++)
        #pragma unroll
        for (int j=0;j<4;j++) { acc1[i][j]=0ull; acc2[i][j]=0ull; }

    int r0 = tid >> 2, kf = tid & 3;
    int wrow0 = n0 + r0;
    int wrow1 = HIDc + n0 + r0;

    {
        float4 a0 = *(const float4*)&A[(size_t)(bm+r0)*K + kf*4];
        float4 a1 = *(const float4*)&A[(size_t)(bm+r0+64)*K + kf*4];
        float4 w0 = *(const float4*)&W[(size_t)wrow0*K + kf*4];
        float4 w1 = *(const float4*)&W[(size_t)wrow1*K + kf*4];
        #pragma unroll
        for (int j=0;j<4;j++) {
            As[0][kf*4+j][r0]    = ((const float*)&a0)[j];
            As[0][kf*4+j][r0+64] = ((const float*)&a1)[j];
            Ws[0][kf*4+j][r0]    = ((const float*)&w0)[j];
            Ws[0][kf*4+j][r0+64] = ((const float*)&w1)[j];
        }
    }
    __syncthreads();

    int nT = K >> 4;
    for (int t0 = 0; t0 < nT; t0++) {
        int cur = t0 & 1;
        float4 pa0, pa1, pw0, pw1;
        bool nx = (t0+1 < nT);
        if (nx) {
            int k0 = (t0+1)*16;
            pa0 = *(const float4*)&A[(size_t)(bm+r0)*K + k0 + kf*4];
            pa1 = *(const float4*)&A[(size_t)(bm+r0+64)*K + k0 + kf*4];
            pw0 = *(const float4*)&W[(size_t)wrow0*K + k0 + kf*4];
            pw1 = *(const float4*)&W[(size_t)wrow1*K + k0 + kf*4];
        }
        #pragma unroll
        for (int kk = 0; kk < 16; kk++) {
            float4 a4a = *(const float4*)&As[cur][kk][ty*8];
            float4 a4b = *(const float4*)&As[cur][kk][ty*8+4];
            float4 b1  = *(const float4*)&Ws[cur][kk][tx*4];
            float4 b2  = *(const float4*)&Ws[cur][kk][64+tx*4];
            unsigned long long a2[4] = {pk2(a4a.x,a4a.y), pk2(a4a.z,a4a.w),
                                        pk2(a4b.x,a4b.y), pk2(a4b.z,a4b.w)};
            unsigned long long bd1[4] = {pk2(b1.x,b1.x), pk2(b1.y,b1.y),
                                         pk2(b1.z,b1.z), pk2(b1.w,b1.w)};
            unsigned long long bd2[4] = {pk2(b2.x,b2.x), pk2(b2.y,b2.y),
                                         pk2(b2.z,b2.z), pk2(b2.w,b2.w)};
            #pragma unroll
            for (int i=0;i<4;i++)
                #pragma unroll
                for (int j=0;j<4;j++) { fma2(acc1[i][j], a2[i], bd1[j]); fma2(acc2[i][j], a2[i], bd2[j]); }
        }
        if (nx) {
            int nb = cur^1;
            #pragma unroll
            for (int j=0;j<4;j++) {
                As[nb][kf*4+j][r0]    = ((const float*)&pa0)[j];
                As[nb][kf*4+j][r0+64] = ((const float*)&pa1)[j];
                Ws[nb][kf*4+j][r0]    = ((const float*)&pw0)[j];
                Ws[nb][kf*4+j][r0+64] = ((const float*)&pw1)[j];
            }
        }
        __syncthreads();
    }
    #pragma unroll
    for (int i=0;i<4;i++) {
        int m = bm + ty*8 + 2*i;
        #pragma unroll
        for (int j=0;j<4;j++) {
            int n = n0 + tx*4 + j;
            float2 v1 = upk2(acc1[i][j]);
            float2 v2 = upk2(acc2[i][j]);
            HS[(size_t)m*HIDc + n]     = v1.x / (1.f + __expf(-v1.x)) * v2.x;
            HS[(size_t)(m+1)*HIDc + n] = v1.y / (1.f + __expf(-v1.y)) * v2.y;
        }
    }
}

// ---------------- rope ----------------
__global__ void k_rope(float* __restrict__ proj) {
    int idx = blockIdx.x*blockDim.x + threadIdx.x;
    if (idx >= BNc*2*Hc*16) return;
    int j = idx & 15; int r = idx >> 4;
    int h = r % Hc;  r /= Hc;
    int qk = r & 1;  int bn = r >> 1;
    int n = bn % Nc;
    float inv = __expf(-((float)j / 16.f) * 9.210340371976184f);
    float ang = (float)n * inv;
    float cs = cosf(ang), sn = sinf(ang);
    float* base = proj + (size_t)bn*PROJc + qk*384 + h*32;
    float x1 = base[j], x2 = base[j+16];
    base[j]    = x1*cs - x2*sn;
    base[j+16] = x1*sn + x2*cs;
}

// ---------------- points ----------------
__global__ void k_points_all(float* __restrict__ proj, const float* __restrict__ rot,
                             const float* __restrict__ trans,
                             float* __restrict__ qn, float* __restrict__ kn) {
    int idx = blockIdx.x*blockDim.x + threadIdx.x;
    if (idx >= BNc*Hc*16) return;
    int p = idx & 15;
    int h = (idx >> 4) % Hc;
    int bn = idx / (16*Hc);
    const float* R = rot + (size_t)bn*9;
    const float* tr = trans + (size_t)bn*3;
    float* base;
    if (p < 4)      base = proj + (size_t)bn*PROJc + 1152 + h*12 + p*3;
    else if (p < 8) base = proj + (size_t)bn*PROJc + 1296 + h*12 + (p-4)*3;
    else            base = proj + (size_t)bn*PROJc + 1440 + h*24 + (p-8)*3;
    float x = base[0], y = base[1], z = base[2];
    float gx = __ldg(&R[0])*x + __ldg(&R[1])*y + __ldg(&R[2])*z + __ldg(&tr[0]);
    float gy = __ldg(&R[3])*x + __ldg(&R[4])*y + __ldg(&R[5])*z + __ldg(&tr[1]);
    float gz = __ldg(&R[6])*x + __ldg(&R[7])*y + __ldg(&R[8])*z + __ldg(&tr[2]);
    base[0]=gx; base[1]=gy; base[2]=gz;
    float nsq = gx*gx + gy*gy + gz*gz;
    nsq += __shfl_xor_sync(0xffffffffu, nsq, 1);
    nsq += __shfl_xor_sync(0xffffffffu, nsq, 2);
    int b = bn / Nc, n = bn % Nc;
    if (p == 0) qn[(b*Hc+h)*Nc + n] = nsq;
    if (p == 4) kn[(b*Hc+h)*Nc + n] = nsq;
}

// ---------------- raw logits (f32x2 micro) ----------------
__global__ __launch_bounds__(256) void k_logits(
        const float* __restrict__ proj, const float* __restrict__ qn,
        const float* __restrict__ kn, const float* __restrict__ head_w,
        float* __restrict__ logits) {
    __shared__ float Qs[32][68], Ks[32][68];
    __shared__ float Qps[12][68], Kps[12][68];
    __shared__ float qns[64], kns[64];
    int bh = blockIdx.z; int h = bh % Hc, b = bh / Hc;
    int q0 = blockIdx.y*64, k0 = blockIdx.x*64;
    int t = threadIdx.x;
    #pragma unroll
    for (int i = 0; i < 2; i++) {
        int idx = i*256 + t;
        int row = idx >> 3, cf = idx & 7;
        float4 qv = *(const float4*)&proj[(size_t)(b*Nc + q0 + row)*PROJc + h*32 + cf*4];
        float4 kv = *(const float4*)&proj[(size_t)(b*Nc + k0 + row)*PROJc + 384 + h*32 + cf*4];
        #pragma unroll
        for (int j=0;j<4;j++) { Qs[cf*4+j][row] = ((const float*)&qv)[j]; Ks[cf*4+j][row] = ((const float*)&kv)[j]; }
    }
    #pragma unroll
    for (int i = 0; i < 3; i++) {
        int idx = i*256 + t;
        if (idx < 768) {
            int row = idx / 12, p = idx % 12;
            Qps[p][row] = proj[(size_t)(b*Nc + q0 + row)*PROJc + 1152 + h*12 + p];
            Kps[p][row] = proj[(size_t)(b*Nc + k0 + row)*PROJc + 1296 + h*12 + p];
        }
    }
    if (t < 64)       qns[t]    = qn[(b*Hc + h)*Nc + q0 + t];
    else if (t < 128) kns[t-64] = kn[(b*Hc + h)*Nc + k0 + (t-64)];
    __syncthreads();

    int ty = t >> 4, tx = t & 15;
    unsigned long long accA[2][4], accB[2][4];
    #pragma unroll
    for (int i=0;i<2;i++)
        #pragma unroll
        for (int j=0;j<4;j++) { accA[i][j]=0ull; accB[i][j]=0ull; }
    #pragma unroll 8
    for (int c = 0; c < 32; c++) {
        float4 a4 = *(const float4*)&Qs[c][ty*4];
        float4 b4 = *(const float4*)&Ks[c][tx*4];
        unsigned long long a2[2] = {pk2(a4.x,a4.y), pk2(a4.z,a4.w)};
        unsigned long long bd[4] = {pk2(b4.x,b4.x), pk2(b4.y,b4.y),
                                    pk2(b4.z,b4.z), pk2(b4.w,b4.w)};
        #pragma unroll
        for (int i=0;i<2;i++)
            #pragma unroll
            for (int j=0;j<4;j++) fma2(accA[i][j], a2[i], bd[j]);
    }
    #pragma unroll
    for (int p = 0; p < 12; p++) {
        float4 a4 = *(const float4*)&Qps[p][ty*4];
        float4 b4 = *(const float4*)&Kps[p][tx*4];
        unsigned long long a2[2] = {pk2(a4.x,a4.y), pk2(a4.z,a4.w)};
        unsigned long long bd[4] = {pk2(b4.x,b4.x), pk2(b4.y,b4.y),
                                    pk2(b4.z,b4.z), pk2(b4.w,b4.w)};
        #pragma unroll
        for (int i=0;i<2;i++)
            #pragma unroll
            for (int j=0;j<4;j++) fma2(accB[i][j], a2[i], bd[j]);
    }
    float gamma = log1pf(__expf(head_w[h]));
    float c2 = 0.5f * WLc * WCc * gamma;
    float cA = WLc * INV_SQRT_CH;
    #pragma unroll
    for (int i=0;i<2;i++) {
        int q = q0 + ty*4 + 2*i;
        #pragma unroll
        for (int j=0;j<4;j++) {
            int k = k0 + tx*4 + j;
            float2 vA = upk2(accA[i][j]);
            float2 vB = upk2(accB[i][j]);
            logits[(((size_t)bh)*Nc + q)*Nc + k] =
                cA*vA.x + 2.f*c2*vB.x - c2*(qns[ty*4+2*i] + kns[tx*4+j]);
            logits[(((size_t)bh)*Nc + q+1)*Nc + k] =
                cA*vA.y + 2.f*c2*vB.y - c2*(qns[ty*4+2*i+1] + kns[tx*4+j]);
        }
    }
}

// ---------------- FUSED z: bias + softmax + opair; z cached once as half2 ----------------
#define ZF_L    0
#define ZF_WS   (12*512)
#define ZF_RS   (ZF_WS + 12*128)
#define ZF_AS   (ZF_RS + 512)
#define ZF_ZH   (ZF_AS + 128*12)
#define ZF_SMEM ((ZF_ZH + 512*68)*4)
__global__ __launch_bounds__(256) void k_zfuse(
        float* __restrict__ att, const float* __restrict__ z,
        const float* __restrict__ nzw, const float* __restrict__ wpair,
        float* __restrict__ cat) {
    extern __shared__ float smf[];
    float* L    = smf + ZF_L;
    float* ws   = smf + ZF_WS;
    float* rsts = smf + ZF_RS;
    float* as   = smf + ZF_AS;
    __half2* zh = (__half2*)(smf + ZF_ZH);
    int bq = blockIdx.x; int b = bq >> 9, q = bq & 511;
    int t = threadIdx.x;

    #pragma unroll
    for (int i = 0; i < 6; i++) {
        int idx = i*256 + t;
        int h = idx >> 7, c = idx & 127;
        ws[h*128 + c] = wpair[h*CZc + c] * nzw[c];
    }
    #pragma unroll
    for (int i = 0; i < 6; i++) {
        int lin = (i*256 + t)*4;
        int h = lin >> 9, k = lin & 511;
        *(float4*)&L[h*512 + k] = *(const float4*)&att[(((size_t)b*Hc + h)*Nc + q)*Nc + k];
    }
    for (int i = 0; i < 64; i++) {
        int idx = i*256 + t;
        int row = idx >> 5, c4 = idx & 31;
        float4 v = *(const float4*)&z[((size_t)bq*Nc + row)*CZc + c4*4];
        zh[row*68 + c4*2    ] = __floats2half2_rn(v.x, v.y);
        zh[row*68 + c4*2 + 1] = __floats2half2_rn(v.z, v.w);
    }
    __syncthreads();

    int rg = t & 63, hg = t >> 6;
    {
        float a[8][3], ssq[8];
        #pragma unroll
        for (int j=0;j<8;j++) { a[j][0]=0;a[j][1]=0;a[j][2]=0; ssq[j]=0; }
        const float* w0 = &ws[(hg*3+0)*128];
        const float* w1 = &ws[(hg*3+1)*128];
        const float* w2 = &ws[(hg*3+2)*128];
        for (int c8 = 0; c8 < 16; c8++) {
            float4 wa0 = *(const float4*)&w0[c8*8], wa1 = *(const float4*)&w0[c8*8+4];
            float4 wb0 = *(const float4*)&w1[c8*8], wb1 = *(const float4*)&w1[c8*8+4];
            float4 wc0 = *(const float4*)&w2[c8*8], wc1 = *(const float4*)&w2[c8*8+4];
            #pragma unroll
            for (int j = 0; j < 8; j++) {
                int row = rg + 64*j;
                uint4 zu = *(const uint4*)&zh[row*68 + c8*4];
                float2 f0 = __half22float2(((const __half2*)&zu)[0]);
                float2 f1 = __half22float2(((const __half2*)&zu)[1]);
                float2 f2 = __half22float2(((const __half2*)&zu)[2]);
                float2 f3 = __half22float2(((const __half2*)&zu)[3]);
                float zv[8] = {f0.x,f0.y,f1.x,f1.y,f2.x,f2.y,f3.x,f3.y};
                float wA[8] = {wa0.x,wa0.y,wa0.z,wa0.w,wa1.x,wa1.y,wa1.z,wa1.w};
                float wB[8] = {wb0.x,wb0.y,wb0.z,wb0.w,wb1.x,wb1.y,wb1.z,wb1.w};
                float wC[8] = {wc0.x,wc0.y,wc0.z,wc0.w,wc1.x,wc1.y,wc1.z,wc1.w};
                #pragma unroll
                for (int e = 0; e < 8; e++) {
                    a[j][0] += zv[e]*wA[e];
                    a[j][1] += zv[e]*wB[e];
                    a[j][2] += zv[e]*wC[e];
                    ssq[j]  += zv[e]*zv[e];
                }
            }
        }
        #pragma unroll
        for (int j=0;j<8;j++) {
            int k = rg + 64*j;
            float rs = rsqrtf(ssq[j]*(1.f/128.f) + 1e-6f);
            float cf = WLc * rs;
            L[(hg*3+0)*512 + k] += cf*a[j][0];
            L[(hg*3+1)*512 + k] += cf*a[j][1];
            L[(hg*3+2)*512 + k] += cf*a[j][2];
            if (hg == 0) rsts[k] = rs;
        }
    }
    __syncthreads();

    int warp = t >> 5, lane = t & 31;
    for (int r = warp; r < 12; r += 8) {
        float* row = &L[r*512];
        float m = -1e30f;
        #pragma unroll
        for (int i = lane; i < 512; i += 32) m = fmaxf(m, row[i]);
        #pragma unroll
        for (int o = 16; o; o >>= 1) m = fmaxf(m, __shfl_xor_sync(0xffffffffu, m, o));
        float s = 0.f;
        #pragma unroll
        for (int i = lane; i < 512; i += 32) { float v = __expf(row[i]-m); row[i] = v; s += v; }
        #pragma unroll
        for (int o = 16; o; o >>= 1) s += __shfl_xor_sync(0xffffffffu, s, o);
        float inv = 1.f/s;
        #pragma unroll
        for (int i = lane; i < 512; i += 32) row[i] *= inv;
    }
    __syncthreads();

    #pragma unroll
    for (int i = 0; i < 6; i++) {
        int lin = (i*256 + t)*4;
        int h = lin >> 9, k = lin & 511;
        *(float4*)&att[(((size_t)b*Hc + h)*Nc + q)*Nc + k] = *(float4*)&L[h*512 + k];
    }

    int cg = t & 31;
    int hg2 = (t >> 5) & 3;
    int ph = t >> 7;
    float acc[3][4];
    #pragma unroll
    for (int j=0;j<3;j++) { acc[j][0]=0;acc[j][1]=0;acc[j][2]=0;acc[j][3]=0; }

    for (int kc = 0; kc < Nc; kc += 128) {
        __syncthreads();
        #pragma unroll
        for (int i = 0; i < 6; i++) {
            int idx = i*256 + t;
            int kk = idx / 12, h = idx % 12;
            as[kk*12 + h] = L[h*512 + kc + kk] * rsts[kc + kk];
        }
        __syncthreads();
        #pragma unroll 4
        for (int kk2 = 0; kk2 < 64; kk2++) {
            int krow = kc + ph*64 + kk2;
            uint2 zu = *(const uint2*)&zh[krow*68 + cg*2];
            float2 fA = __half22float2(((const __half2*)&zu)[0]);
            float2 fB = __half22float2(((const __half2*)&zu)[1]);
            const float* ap = &as[(ph*64 + kk2)*12 + hg2*3];
            float b0 = ap[0], b1 = ap[1], b2 = ap[2];
            acc[0][0] += b0*fA.x; acc[0][1] += b0*fA.y; acc[0][2] += b0*fB.x; acc[0][3] += b0*fB.y;
            acc[1][0] += b1*fA.x; acc[1][1] += b1*fA.y; acc[1][2] += b1*fB.x; acc[1][3] += b1*fB.y;
            acc[2][0] += b2*fA.x; acc[2][1] += b2*fA.y; acc[2][2] += b2*fB.x; acc[2][3] += b2*fB.y;
        }
    }
    __syncthreads();
    if (ph == 1) {
        float* red = &ws[(t & 127)*12];
        #pragma unroll
        for (int j=0;j<3;j++)
            #pragma unroll
            for (int i=0;i<4;i++) red[j*4+i] = acc[j][i];
    }
    __syncthreads();
    if (ph == 0) {
        const float* red = &ws[t*12];
        float4 nw = *(const float4*)&nzw[cg*4];
        float nv[4] = {nw.x, nw.y, nw.z, nw.w};
        float* cc = cat + (size_t)bq*CATc + 768;
        #pragma unroll
        for (int j=0;j<3;j++) {
            int h = hg2*3 + j;
            #pragma unroll
            for (int i=0;i<4;i++)
                cc[h*CZc + cg*4 + i] = (acc[j][i] + red[j*4+i]) * nv[i];
        }
    }
}

// ---------------- AV (split-K over k): 128 thr, 4q x 7c (f32x2) ----------------
__global__ __launch_bounds__(128) void k_av(
        const float* __restrict__ att, const float* __restrict__ proj,
        float* __restrict__ P0, float* __restrict__ P1) {
    __shared__ float As[32][68];
    __shared__ float Ws[32][57];
    int bh = blockIdx.y; int h = bh % Hc, b = bh / Hc;
    int q0 = blockIdx.x*64;
    int zh = blockIdx.z;
    float* P = zh ? P1 : P0;
    int t = threadIdx.x;
    int cg = t >> 4, qg = t & 15;
    unsigned long long acc[2][7];
    #pragma unroll
    for (int i=0;i<2;i++)
        #pragma unroll
        for (int j=0;j<7;j++) acc[i][j]=0ull;

    int kbeg = zh*256, kend = kbeg + 256;
    for (int kc = kbeg; kc < kend; kc += 32) {
        #pragma unroll
        for (int i = 0; i < 4; i++) {
            int idx = i*128 + t;
            int q = idx >> 3, kf = idx & 7;
            float4 v = *(const float4*)&att[(((size_t)bh)*Nc + q0 + q)*Nc + kc + kf*4];
            #pragma unroll
            for (int j=0;j<4;j++) As[kf*4+j][q] = ((const float*)&v)[j];
        }
        #pragma unroll
        for (int i = 0; i < 14; i++) {
            int idx = i*128 + t;
            if (idx < 32*56) {
                int kk = idx / 56, c = idx % 56;
                int kg = kc + kk;
                float val;
                if (c < 32) val = proj[(size_t)(b*Nc + kg)*PROJc + 768 + h*32 + c];
                else        val = proj[(size_t)(b*Nc + kg)*PROJc + 1440 + h*24 + (c-32)];
                Ws[kk][c] = val;
            }
        }
        __syncthreads();
        #pragma unroll 4
        for (int kk = 0; kk < 32; kk++) {
            float4 a4 = *(const float4*)&As[kk][qg*4];
            unsigned long long a2[2] = {pk2(a4.x,a4.y), pk2(a4.z,a4.w)};
            #pragma unroll
            for (int j=0;j<7;j++) {
                float w = Ws[kk][cg*7+j];
                unsigned long long bd = pk2(w, w);
                fma2(acc[0][j], a2[0], bd);
                fma2(acc[1][j], a2[1], bd);
            }
        }
        __syncthreads();
    }
    #pragma unroll
    for (int i=0;i<2;i++) {
        int q = q0 + qg*4 + 2*i;
        #pragma unroll
        for (int j=0;j<7;j++) {
            int c = cg*7 + j;
            float2 v = upk2(acc[i][j]);
            P[((size_t)(b*Nc + q)*Hc + h)*56 + c]   = v.x;
            P[((size_t)(b*Nc + q+1)*Hc + h)*56 + c] = v.y;
        }
    }
}

// ---------------- AV reduce + op->local fused ----------------
__global__ void k_avred_op(const float* __restrict__ P0, const float* __restrict__ P1,
                           const float* __restrict__ rot, const float* __restrict__ trans,
                           float* __restrict__ cat) {
    int idx = blockIdx.x*blockDim.x + threadIdx.x;
    const int total_o = BNc*Hc*32;
    if (idx < total_o) {
        int c = idx & 31; int r = idx >> 5;
        int h = r % Hc; int bq = r / Hc;
        size_t pi = ((size_t)bq*Hc + h)*56 + c;
        cat[(size_t)bq*CATc + h*32 + c] = P0[pi] + P1[pi];
    } else {
        int j = idx - total_o;
        if (j >= BNc*Hc*PVc) return;
        int p = j & 7; int r = j >> 3;
        int h = r % Hc; int bq = r / Hc;
        size_t pi = ((size_t)bq*Hc + h)*56 + 32 + p*3;
        float x = P0[pi+0] + P1[pi+0];
        float y = P0[pi+1] + P1[pi+1];
        float zv = P0[pi+2] + P1[pi+2];
        const float* R = rot + (size_t)bq*9;
        const float* tr = trans + (size_t)bq*3;
        x -= tr[0]; y -= tr[1]; zv -= tr[2];
        float lx = R[0]*x + R[3]*y + R[6]*zv;
        float ly = R[1]*x + R[4]*y + R[7]*zv;
        float lz = R[2]*x + R[5]*y + R[8]*zv;
        float* cc = cat + (size_t)bq*CATc;
        cc[384 + h*24 + p*3+0] = lx;
        cc[384 + h*24 + p*3+1] = ly;
        cc[384 + h*24 + p*3+2] = lz;
        cc[672 + h*8 + p] = sqrtf(lx*lx + ly*ly + lz*lz + 1e-8f);
    }
}

__global__ void k_frame(const float* __restrict__ x, const float* __restrict__ wf,
                        const float* __restrict__ rot, const float* __restrict__ trans,
                        float* __restrict__ out_rot, float* __restrict__ out_trans) {
    int warp = (blockIdx.x*blockDim.x + threadIdx.x) >> 5;
    int lane = threadIdx.x & 31;
    if (warp >= BNc) return;
    const float* xr = x + (size_t)warp*CSc;
    float v[6];
    #pragma unroll
    for (int o = 0; o < 6; o++) {
        float d = 0.f;
        for (int c = lane; c < CSc; c += 32) d += xr[c]*wf[o*CSc + c];
        #pragma unroll
        for (int off = 16; off; off >>= 1) d += __shfl_xor_sync(0xffffffffu, d, off);
        v[o] = d;
    }
    if (lane == 0) {
        float qx = v[0], qy = v[1], qz = v[2];
        float inv = rsqrtf(1.f + qx*qx + qy*qy + qz*qz);
        float qw = inv; qx *= inv; qy *= inv; qz *= inv;
        float U[9] = {
            1-2*(qy*qy+qz*qz), 2*(qx*qy-qw*qz), 2*(qx*qz+qw*qy),
            2*(qx*qy+qw*qz), 1-2*(qx*qx+qz*qz), 2*(qy*qz-qw*qx),
            2*(qx*qz-qw*qy), 2*(qy*qz+qw*qx), 1-2*(qx*qx+qy*qy)};
        const float* R = rot + (size_t)warp*9;
        float* Ro = out_rot + (size_t)warp*9;
        #pragma unroll
        for (int i = 0; i < 3; i++)
            #pragma unroll
            for (int j = 0; j < 3; j++)
                Ro[i*3+j] = R[i*3+0]*U[0*3+j] + R[i*3+1]*U[1*3+j] + R[i*3+2]*U[2*3+j];
        const float* t = trans + (size_t)warp*3;
        float* To = out_trans + (size_t)warp*3;
        #pragma unroll
        for (int i = 0; i < 3; i++)
            To[i] = R[i*3+0]*v[3] + R[i*3+1]*v[4] + R[i*3+2]*v[5] + t[i];
    }
}

// ---------------- launch ----------------
static float* sym(const void* s) {
    void* p = nullptr;
    cudaGetSymbolAddress(&p, s);
    return (float*)p;
}

extern "C" void kernel_launch(void* const* d_in, const int* in_sizes, int n_in,
                              void* d_out, int out_size) {
    (void)in_sizes; (void)n_in; (void)out_size;
    const float* in_s    = (const float*)d_in[0];
    const float* rot     = (const float*)d_in[1];
    const float* trans   = (const float*)d_in[2];
    const float* z       = (const float*)d_in[3];
    const float* norm_z_w = (const float*)d_in[5];
    const float* norm1_w  = (const float*)d_in[6];
    const float* norm2_w  = (const float*)d_in[7];
    const float* norm3_w  = (const float*)d_in[8];
    const float* w_qkv    = (const float*)d_in[9];
    const float* w_qpts   = (const float*)d_in[10];
    const float* w_kpts   = (const float*)d_in[11];
    const float* w_vpts   = (const float*)d_in[12];
    const float* head_w   = (const float*)d_in[13];
    const float* w_pair   = (const float*)d_in[14];
    const float* w_out    = (const float*)d_in[15];
    const float* w12      = (const float*)d_in[16];
    const float* w3       = (const float*)d_in[17];
    const float* w_frame  = (const float*)d_in[18];

    float* out       = (float*)d_out;
    float* out_s     = out;
    float* out_rot   = out + BNc*CSc;
    float* out_trans = out + BNc*CSc + BNc*9;

    float* s0   = sym(g_s0);
    float* proj = sym(g_proj);
    float* qn   = sym(g_qn);
    float* kn   = sym(g_kn);
    float* att  = sym(g_att);
    float* cat  = sym(g_cat);
    float* x    = sym(g_x);
    float* hs   = sym(g_hs);
    float* p0   = sym(g_p0);
    float* p1   = sym(g_p1);
    float* p2   = sym(g_p2);
    float* avp0 = sym(g_avp0);
    float* avp1 = sym(g_avp1);

    cudaFuncSetAttribute(k_zfuse, cudaFuncAttributeMaxDynamicSharedMemorySize, ZF_SMEM);

    k_rmsnorm<<<BNc/8, 256>>>(in_s, norm1_w, s0, BNc, CSc);

    k_proj<<<dim3(PROJc/64, BNc/128), 256>>>(s0, w_qkv, w_qpts, w_kpts, w_vpts, proj);

    k_rope<<<(BNc*2*Hc*16)/256, 256>>>(proj);
    k_points_all<<<(BNc*Hc*16)/256, 256>>>(proj, rot, trans, qn, kn);

    k_logits<<<dim3(Nc/64, Nc/64, Bc*Hc), 256>>>(proj, qn, kn, head_w, att);

    k_zfuse<<<BNc, 256, ZF_SMEM>>>(att, z, norm_z_w, w_pair, cat);

    k_av<<<dim3(Nc/64, Bc*Hc, 2), 128>>>(att, proj, avp0, avp1);
    k_avred_op<<<(BNc*Hc*40 + 255)/256, 256>>>(avp0, avp1, rot, trans, cat);

    k_gemmK<<<dim3(CSc/64, BNc/128, 3), 256>>>(cat, w_out, p0, p1, p2, CSc, CATc, 768);
    k_reduce3<<<(BNc*CSc/4 + 255)/256, 256>>>(in_s, p0, p1, p2, out_s);

    k_rmsnorm<<<BNc/8, 256>>>(out_s, norm2_w, x, BNc, CSc);
    k_glu<<<dim3(HIDc/64, BNc/128), 256>>>(x, w12, hs, CSc);

    k_gemmK<<<dim3(CSc/64, BNc/128, 3), 256>>>(hs, w3, p0, p1, p2, CSc, HIDc, 512);
    k_reduce3<<<(BNc*CSc/4 + 255)/256, 256>>>(out_s, p0, p1, p2, out_s);

    k_rmsnorm<<<BNc/8, 256>>>(out_s, norm3_w, x, BNc, CSc);
    k_frame<<<BNc/8, 256>>>(x, w_frame, rot, trans, out_rot, out_trans);
}

// round 15
// speedup vs baseline: 1.0567x; 1.0567x over previous
#include <cuda_runtime.h>
#include <cuda_bf16.h>
#include <cuda_fp16.h>
#include <math.h>

// ---------------- constants ----------------
#define Bc   2
#define Nc   512
#define CSc  384
#define CZc  128
#define Hc   12
#define CHc  32
#define PQc  4
#define PVc  8
#define HIDc 1536
#define BNc  (Bc*Nc)          // 1024
#define CATc 2304
#define PROJc 1728            // 1152 qkv | 144 qp | 144 kp | 288 vp

#define WLc  0.5773502691896258f
#define WCc  0.23570226039551587f
#define INV_SQRT_CH 0.17677669529663687f

// ---------------- scratch ----------------
__device__ float g_s0  [BNc*CSc];
__device__ float g_proj[BNc*PROJc];
__device__ float g_qn  [Bc*Hc*Nc];
__device__ float g_kn  [Bc*Hc*Nc];
__device__ float g_att [(size_t)Bc*Hc*Nc*Nc];
__device__ float g_cat [BNc*CATc];
__device__ float g_x   [BNc*CSc];
__device__ float g_hs  [BNc*HIDc];
__device__ float g_p0  [BNc*CSc];
__device__ float g_p1  [BNc*CSc];
__device__ float g_p2  [BNc*CSc];
__device__ float g_avp0[BNc*Hc*56];
__device__ float g_avp1[BNc*Hc*56];

// ---------------- rmsnorm ----------------
__global__ void k_rmsnorm(const float* __restrict__ in, const float* __restrict__ w,
                          float* __restrict__ out, int rows, int C) {
    int warp = (blockIdx.x*blockDim.x + threadIdx.x) >> 5;
    int lane = threadIdx.x & 31;
    if (warp >= rows) return;
    const float* x = in + (size_t)warp*C;
    float ss = 0.f;
    for (int c = lane; c < C; c += 32) { float v = x[c]; ss += v*v; }
    #pragma unroll
    for (int o = 16; o; o >>= 1) ss += __shfl_xor_sync(0xffffffffu, ss, o);
    float scale = rsqrtf(ss/(float)C + 1e-6f);
    float* y = out + (size_t)warp*C;
    for (int c = lane; c < C; c += 32) y[c] = x[c]*scale*w[c];
}

// ---------------- fused projection GEMM: BM=128 BN=64, 8x4 micro ----------------
__global__ __launch_bounds__(256) void k_proj(
        const float* __restrict__ A,
        const float* __restrict__ Wqkv, const float* __restrict__ Wqp,
        const float* __restrict__ Wkp,  const float* __restrict__ Wvp,
        float* __restrict__ P) {
    __shared__ float As[2][16][132];
    __shared__ float Ws[2][16][68];
    const int K = CSc;
    int tid = threadIdx.x;
    int bm = blockIdx.y*128, col0 = blockIdx.x*64;
    int ty = tid >> 4, tx = tid & 15;
    float acc[8][4];
    #pragma unroll
    for (int i=0;i<8;i++) { acc[i][0]=0;acc[i][1]=0;acc[i][2]=0;acc[i][3]=0; }

    int r0 = tid >> 2, kf = tid & 3;
    int col = col0 + r0;
    const float* wrowp;
    if (col < 1152)      wrowp = Wqkv + (size_t)col*K;
    else if (col < 1296) wrowp = Wqp  + (size_t)(col-1152)*K;
    else if (col < 1440) wrowp = Wkp  + (size_t)(col-1296)*K;
    else                 wrowp = Wvp  + (size_t)(col-1440)*K;
    const float* a0p = A + (size_t)(bm+r0)*K;
    const float* a1p = A + (size_t)(bm+r0+64)*K;

    {
        float4 a0 = *(const float4*)&a0p[kf*4];
        float4 a1 = *(const float4*)&a1p[kf*4];
        float4 w0 = *(const float4*)&wrowp[kf*4];
        #pragma unroll
        for (int j=0;j<4;j++) {
            As[0][kf*4+j][r0]    = ((const float*)&a0)[j];
            As[0][kf*4+j][r0+64] = ((const float*)&a1)[j];
            Ws[0][kf*4+j][r0]    = ((const float*)&w0)[j];
        }
    }
    __syncthreads();

    int nT = K >> 4;
    for (int t0 = 0; t0 < nT; t0++) {
        int cur = t0 & 1;
        float4 pa0, pa1, pw0;
        bool nx = (t0+1 < nT);
        if (nx) {
            int k0 = (t0+1)*16;
            pa0 = *(const float4*)&a0p[k0 + kf*4];
            pa1 = *(const float4*)&a1p[k0 + kf*4];
            pw0 = *(const float4*)&wrowp[k0 + kf*4];
        }
        #pragma unroll
        for (int kk = 0; kk < 16; kk++) {
            float4 a4a = *(const float4*)&As[cur][kk][ty*8];
            float4 a4b = *(const float4*)&As[cur][kk][ty*8+4];
            float4 b4  = *(const float4*)&Ws[cur][kk][tx*4];
            float a[8] = {a4a.x,a4a.y,a4a.z,a4a.w,a4b.x,a4b.y,a4b.z,a4b.w};
            float b[4] = {b4.x,b4.y,b4.z,b4.w};
            #pragma unroll
            for (int i=0;i<8;i++)
                #pragma unroll
                for (int j=0;j<4;j++) acc[i][j] += a[i]*b[j];
        }
        if (nx) {
            int nb = cur^1;
            #pragma unroll
            for (int j=0;j<4;j++) {
                As[nb][kf*4+j][r0]    = ((const float*)&pa0)[j];
                As[nb][kf*4+j][r0+64] = ((const float*)&pa1)[j];
                Ws[nb][kf*4+j][r0]    = ((const float*)&pw0)[j];
            }
        }
        __syncthreads();
    }
    #pragma unroll
    for (int i=0;i<8;i++) {
        int m = bm + ty*8 + i;
        #pragma unroll
        for (int j=0;j<4;j++)
            P[(size_t)m*PROJc + col0 + tx*4 + j] = acc[i][j];
    }
}

// ---------------- split-K GEMM: BM=128 BN=64, 8x4 micro ----------------
__global__ __launch_bounds__(256) void k_gemmK(
        const float* __restrict__ A, const float* __restrict__ W,
        float* __restrict__ P0, float* __restrict__ P1, float* __restrict__ P2,
        int Nd, int K, int klen) {
    __shared__ float As[2][16][132];
    __shared__ float Ws[2][16][68];
    int tid = threadIdx.x;
    int bm = blockIdx.y*128, bn = blockIdx.x*64;
    int kofs = blockIdx.z * klen;
    float* P = (blockIdx.z == 0) ? P0 : (blockIdx.z == 1 ? P1 : P2);
    int ty = tid >> 4, tx = tid & 15;
    float acc[8][4];
    #pragma unroll
    for (int i=0;i<8;i++) { acc[i][0]=0;acc[i][1]=0;acc[i][2]=0;acc[i][3]=0; }

    int r0 = tid >> 2, kf = tid & 3;
    const float* a0p = A + (size_t)(bm+r0)*K + kofs;
    const float* a1p = A + (size_t)(bm+r0+64)*K + kofs;
    const float* wp  = W + (size_t)(bn+r0)*K + kofs;

    {
        float4 a0 = *(const float4*)&a0p[kf*4];
        float4 a1 = *(const float4*)&a1p[kf*4];
        float4 w0 = *(const float4*)&wp[kf*4];
        #pragma unroll
        for (int j=0;j<4;j++) {
            As[0][kf*4+j][r0]    = ((const float*)&a0)[j];
            As[0][kf*4+j][r0+64] = ((const float*)&a1)[j];
            Ws[0][kf*4+j][r0]    = ((const float*)&w0)[j];
        }
    }
    __syncthreads();

    int nT = klen >> 4;
    for (int t0 = 0; t0 < nT; t0++) {
        int cur = t0 & 1;
        float4 pa0, pa1, pw0;
        bool nx = (t0+1 < nT);
        if (nx) {
            int k0 = (t0+1)*16;
            pa0 = *(const float4*)&a0p[k0 + kf*4];
            pa1 = *(const float4*)&a1p[k0 + kf*4];
            pw0 = *(const float4*)&wp[k0 + kf*4];
        }
        #pragma unroll
        for (int kk = 0; kk < 16; kk++) {
            float4 a4a = *(const float4*)&As[cur][kk][ty*8];
            float4 a4b = *(const float4*)&As[cur][kk][ty*8+4];
            float4 b4  = *(const float4*)&Ws[cur][kk][tx*4];
            float a[8] = {a4a.x,a4a.y,a4a.z,a4a.w,a4b.x,a4b.y,a4b.z,a4b.w};
            float b[4] = {b4.x,b4.y,b4.z,b4.w};
            #pragma unroll
            for (int i=0;i<8;i++)
                #pragma unroll
                for (int j=0;j<4;j++) acc[i][j] += a[i]*b[j];
        }
        if (nx) {
            int nb = cur^1;
            #pragma unroll
            for (int j=0;j<4;j++) {
                As[nb][kf*4+j][r0]    = ((const float*)&pa0)[j];
                As[nb][kf*4+j][r0+64] = ((const float*)&pa1)[j];
                Ws[nb][kf*4+j][r0]    = ((const float*)&pw0)[j];
            }
        }
        __syncthreads();
    }
    #pragma unroll
    for (int i=0;i<8;i++) {
        int m = bm + ty*8 + i;
        #pragma unroll
        for (int j=0;j<4;j++)
            P[(size_t)m*Nd + bn + tx*4 + j] = acc[i][j];
    }
}

// ---------------- fused reduce3 + rmsnorm: out = Cadd+p0+p1+p2; x = rmsnorm(out)*w ----------------
__global__ __launch_bounds__(256) void k_red3norm(
        const float* __restrict__ Cadd,
        const float* __restrict__ p0, const float* __restrict__ p1,
        const float* __restrict__ p2, const float* __restrict__ w,
        float* __restrict__ out, float* __restrict__ x) {
    int warp = (blockIdx.x*blockDim.x + threadIdx.x) >> 5;
    int lane = threadIdx.x & 31;
    if (warp >= BNc) return;
    size_t base = (size_t)warp*CSc;
    float4 v[3];
    float ss = 0.f;
    #pragma unroll
    for (int i = 0; i < 3; i++) {
        int c = lane*4 + i*128;
        float4 cc = *(const float4*)&Cadd[base + c];
        float4 a = *(const float4*)&p0[base + c];
        float4 b = *(const float4*)&p1[base + c];
        float4 d = *(const float4*)&p2[base + c];
        float4 o;
        o.x = cc.x + a.x + b.x + d.x;
        o.y = cc.y + a.y + b.y + d.y;
        o.z = cc.z + a.z + b.z + d.z;
        o.w = cc.w + a.w + b.w + d.w;
        *(float4*)&out[base + c] = o;
        v[i] = o;
        ss += o.x*o.x + o.y*o.y + o.z*o.z + o.w*o.w;
    }
    #pragma unroll
    for (int o = 16; o; o >>= 1) ss += __shfl_xor_sync(0xffffffffu, ss, o);
    float scale = rsqrtf(ss/(float)CSc + 1e-6f);
    #pragma unroll
    for (int i = 0; i < 3; i++) {
        int c = lane*4 + i*128;
        float4 wv = *(const float4*)&w[c];
        float4 o;
        o.x = v[i].x*scale*wv.x;
        o.y = v[i].y*scale*wv.y;
        o.z = v[i].z*scale*wv.z;
        o.w = v[i].w*scale*wv.w;
        *(float4*)&x[base + c] = o;
    }
}

// ---------------- GLU GEMM: BM=128 BN=64 ----------------
__global__ __launch_bounds__(256) void k_glu(
        const float* __restrict__ A, const float* __restrict__ W,
        float* __restrict__ HS, int K) {
    __shared__ float As[2][16][132];
    __shared__ float Ws[2][16][132];
    int tid = threadIdx.x;
    int bm = blockIdx.y*128, n0 = blockIdx.x*64;
    int ty = tid >> 4, tx = tid & 15;
    float acc1[8][4], acc2[8][4];
    #pragma unroll
    for (int i=0;i<8;i++)
        #pragma unroll
        for (int j=0;j<4;j++) { acc1[i][j]=0; acc2[i][j]=0; }

    int r0 = tid >> 2, kf = tid & 3;
    int wrow0 = n0 + r0;
    int wrow1 = HIDc + n0 + r0;

    {
        float4 a0 = *(const float4*)&A[(size_t)(bm+r0)*K + kf*4];
        float4 a1 = *(const float4*)&A[(size_t)(bm+r0+64)*K + kf*4];
        float4 w0 = *(const float4*)&W[(size_t)wrow0*K + kf*4];
        float4 w1 = *(const float4*)&W[(size_t)wrow1*K + kf*4];
        #pragma unroll
        for (int j=0;j<4;j++) {
            As[0][kf*4+j][r0]    = ((const float*)&a0)[j];
            As[0][kf*4+j][r0+64] = ((const float*)&a1)[j];
            Ws[0][kf*4+j][r0]    = ((const float*)&w0)[j];
            Ws[0][kf*4+j][r0+64] = ((const float*)&w1)[j];
        }
    }
    __syncthreads();

    int nT = K >> 4;
    for (int t0 = 0; t0 < nT; t0++) {
        int cur = t0 & 1;
        float4 pa0, pa1, pw0, pw1;
        bool nx = (t0+1 < nT);
        if (nx) {
            int k0 = (t0+1)*16;
            pa0 = *(const float4*)&A[(size_t)(bm+r0)*K + k0 + kf*4];
            pa1 = *(const float4*)&A[(size_t)(bm+r0+64)*K + k0 + kf*4];
            pw0 = *(const float4*)&W[(size_t)wrow0*K + k0 + kf*4];
            pw1 = *(const float4*)&W[(size_t)wrow1*K + k0 + kf*4];
        }
        #pragma unroll
        for (int kk = 0; kk < 16; kk++) {
            float4 a4a = *(const float4*)&As[cur][kk][ty*8];
            float4 a4b = *(const float4*)&As[cur][kk][ty*8+4];
            float4 b1  = *(const float4*)&Ws[cur][kk][tx*4];
            float4 b2  = *(const float4*)&Ws[cur][kk][64+tx*4];
            float a[8] = {a4a.x,a4a.y,a4a.z,a4a.w,a4b.x,a4b.y,a4b.z,a4b.w};
            float c1[4] = {b1.x,b1.y,b1.z,b1.w};
            float c2[4] = {b2.x,b2.y,b2.z,b2.w};
            #pragma unroll
            for (int i=0;i<8;i++)
                #pragma unroll
                for (int j=0;j<4;j++) { acc1[i][j] += a[i]*c1[j]; acc2[i][j] += a[i]*c2[j]; }
        }
        if (nx) {
            int nb = cur^1;
            #pragma unroll
            for (int j=0;j<4;j++) {
                As[nb][kf*4+j][r0]    = ((const float*)&pa0)[j];
                As[nb][kf*4+j][r0+64] = ((const float*)&pa1)[j];
                Ws[nb][kf*4+j][r0]    = ((const float*)&pw0)[j];
                Ws[nb][kf*4+j][r0+64] = ((const float*)&pw1)[j];
            }
        }
        __syncthreads();
    }
    #pragma unroll
    for (int i=0;i<8;i++) {
        int m = bm + ty*8 + i;
        #pragma unroll
        for (int j=0;j<4;j++) {
            int n = n0 + tx*4 + j;
            float h1 = acc1[i][j], h2 = acc2[i][j];
            HS[(size_t)m*HIDc + n] = h1 / (1.f + __expf(-h1)) * h2;
        }
    }
}

// ---------------- fused rope + points: thread = (bn, h, j<16) ----------------
__global__ void k_ropepoints(float* __restrict__ proj, const float* __restrict__ rot,
                             const float* __restrict__ trans,
                             float* __restrict__ qn, float* __restrict__ kn) {
    int idx = blockIdx.x*blockDim.x + threadIdx.x;
    if (idx >= BNc*Hc*16) return;
    int j = idx & 15;
    int h = (idx >> 4) % Hc;
    int bn = idx / (16*Hc);
    int n = bn % Nc;

    // rope on q and k channel pair j
    float inv = __expf(-((float)j / 16.f) * 9.210340371976184f);
    float ang = (float)n * inv;
    float cs = cosf(ang), sn = sinf(ang);
    float* qb = proj + (size_t)bn*PROJc + h*32;
    float x1 = qb[j], x2 = qb[j+16];
    qb[j]    = x1*cs - x2*sn;
    qb[j+16] = x1*sn + x2*cs;
    float* kb = proj + (size_t)bn*PROJc + 384 + h*32;
    x1 = kb[j]; x2 = kb[j+16];
    kb[j]    = x1*cs - x2*sn;
    kb[j+16] = x1*sn + x2*cs;

    // point p=j transform
    const float* R = rot + (size_t)bn*9;
    const float* tr = trans + (size_t)bn*3;
    float* base;
    if (j < 4)      base = proj + (size_t)bn*PROJc + 1152 + h*12 + j*3;
    else if (j < 8) base = proj + (size_t)bn*PROJc + 1296 + h*12 + (j-4)*3;
    else            base = proj + (size_t)bn*PROJc + 1440 + h*24 + (j-8)*3;
    float x = base[0], y = base[1], z = base[2];
    float gx = __ldg(&R[0])*x + __ldg(&R[1])*y + __ldg(&R[2])*z + __ldg(&tr[0]);
    float gy = __ldg(&R[3])*x + __ldg(&R[4])*y + __ldg(&R[5])*z + __ldg(&tr[1]);
    float gz = __ldg(&R[6])*x + __ldg(&R[7])*y + __ldg(&R[8])*z + __ldg(&tr[2]);
    base[0]=gx; base[1]=gy; base[2]=gz;
    float nsq = gx*gx + gy*gy + gz*gz;
    nsq += __shfl_xor_sync(0xffffffffu, nsq, 1);
    nsq += __shfl_xor_sync(0xffffffffu, nsq, 2);
    int b = bn / Nc;
    if (j == 0) qn[(b*Hc+h)*Nc + n] = nsq;
    if (j == 4) kn[(b*Hc+h)*Nc + n] = nsq;
}

// ---------------- raw logits ----------------
__global__ __launch_bounds__(256) void k_logits(
        const float* __restrict__ proj, const float* __restrict__ qn,
        const float* __restrict__ kn, const float* __restrict__ head_w,
        float* __restrict__ logits) {
    __shared__ float Qs[32][68], Ks[32][68];
    __shared__ float Qps[12][68], Kps[12][68];
    __shared__ float qns[64], kns[64];
    int bh = blockIdx.z; int h = bh % Hc, b = bh / Hc;
    int q0 = blockIdx.y*64, k0 = blockIdx.x*64;
    int t = threadIdx.x;
    #pragma unroll
    for (int i = 0; i < 2; i++) {
        int idx = i*256 + t;
        int row = idx >> 3, cf = idx & 7;
        float4 qv = *(const float4*)&proj[(size_t)(b*Nc + q0 + row)*PROJc + h*32 + cf*4];
        float4 kv = *(const float4*)&proj[(size_t)(b*Nc + k0 + row)*PROJc + 384 + h*32 + cf*4];
        #pragma unroll
        for (int j=0;j<4;j++) { Qs[cf*4+j][row] = ((const float*)&qv)[j]; Ks[cf*4+j][row] = ((const float*)&kv)[j]; }
    }
    #pragma unroll
    for (int i = 0; i < 3; i++) {
        int idx = i*256 + t;
        if (idx < 768) {
            int row = idx / 12, p = idx % 12;
            Qps[p][row] = proj[(size_t)(b*Nc + q0 + row)*PROJc + 1152 + h*12 + p];
            Kps[p][row] = proj[(size_t)(b*Nc + k0 + row)*PROJc + 1296 + h*12 + p];
        }
    }
    if (t < 64)       qns[t]    = qn[(b*Hc + h)*Nc + q0 + t];
    else if (t < 128) kns[t-64] = kn[(b*Hc + h)*Nc + k0 + (t-64)];
    __syncthreads();

    int ty = t >> 4, tx = t & 15;
    float accA[4][4], accB[4][4];
    #pragma unroll
    for (int i=0;i<4;i++)
        #pragma unroll
        for (int j=0;j<4;j++) { accA[i][j]=0; accB[i][j]=0; }
    #pragma unroll 8
    for (int c = 0; c < 32; c++) {
        float4 a4 = *(const float4*)&Qs[c][ty*4];
        float4 b4 = *(const float4*)&Ks[c][tx*4];
        float a[4]={a4.x,a4.y,a4.z,a4.w}, bb[4]={b4.x,b4.y,b4.z,b4.w};
        #pragma unroll
        for (int i=0;i<4;i++)
            #pragma unroll
            for (int j=0;j<4;j++) accA[i][j] += a[i]*bb[j];
    }
    #pragma unroll
    for (int p = 0; p < 12; p++) {
        float4 a4 = *(const float4*)&Qps[p][ty*4];
        float4 b4 = *(const float4*)&Kps[p][tx*4];
        float a[4]={a4.x,a4.y,a4.z,a4.w}, bb[4]={b4.x,b4.y,b4.z,b4.w};
        #pragma unroll
        for (int i=0;i<4;i++)
            #pragma unroll
            for (int j=0;j<4;j++) accB[i][j] += a[i]*bb[j];
    }
    float gamma = log1pf(__expf(head_w[h]));
    float c2 = 0.5f * WLc * WCc * gamma;
    float cA = WLc * INV_SQRT_CH;
    #pragma unroll
    for (int i=0;i<4;i++) {
        int q = q0 + ty*4 + i;
        #pragma unroll
        for (int j=0;j<4;j++) {
            int k = k0 + tx*4 + j;
            size_t o = (((size_t)bh)*Nc + q)*Nc + k;
            logits[o] = cA*accA[i][j] + 2.f*c2*accB[i][j] - c2*(qns[ty*4+i] + kns[tx*4+j]);
        }
    }
}

// ---------------- FUSED z: bias + softmax + opair; z cached once as half2 ----------------
#define ZF_L    0
#define ZF_WS   (12*512)
#define ZF_RS   (ZF_WS + 12*128)
#define ZF_AS   (ZF_RS + 512)
#define ZF_ZH   (ZF_AS + 128*12)
#define ZF_SMEM ((ZF_ZH + 512*68)*4)
__global__ __launch_bounds__(256) void k_zfuse(
        float* __restrict__ att, const float* __restrict__ z,
        const float* __restrict__ nzw, const float* __restrict__ wpair,
        float* __restrict__ cat) {
    extern __shared__ float smf[];
    float* L    = smf + ZF_L;
    float* ws   = smf + ZF_WS;
    float* rsts = smf + ZF_RS;
    float* as   = smf + ZF_AS;
    __half2* zh = (__half2*)(smf + ZF_ZH);
    int bq = blockIdx.x; int b = bq >> 9, q = bq & 511;
    int t = threadIdx.x;

    #pragma unroll
    for (int i = 0; i < 6; i++) {
        int idx = i*256 + t;
        int h = idx >> 7, c = idx & 127;
        ws[h*128 + c] = wpair[h*CZc + c] * nzw[c];
    }
    #pragma unroll
    for (int i = 0; i < 6; i++) {
        int lin = (i*256 + t)*4;
        int h = lin >> 9, k = lin & 511;
        *(float4*)&L[h*512 + k] = *(const float4*)&att[(((size_t)b*Hc + h)*Nc + q)*Nc + k];
    }
    for (int i = 0; i < 64; i++) {
        int idx = i*256 + t;
        int row = idx >> 5, c4 = idx & 31;
        float4 v = *(const float4*)&z[((size_t)bq*Nc + row)*CZc + c4*4];
        zh[row*68 + c4*2    ] = __floats2half2_rn(v.x, v.y);
        zh[row*68 + c4*2 + 1] = __floats2half2_rn(v.z, v.w);
    }
    __syncthreads();

    int rg = t & 63, hg = t >> 6;
    {
        float a[8][3], ssq[8];
        #pragma unroll
        for (int j=0;j<8;j++) { a[j][0]=0;a[j][1]=0;a[j][2]=0; ssq[j]=0; }
        const float* w0 = &ws[(hg*3+0)*128];
        const float* w1 = &ws[(hg*3+1)*128];
        const float* w2 = &ws[(hg*3+2)*128];
        for (int c8 = 0; c8 < 16; c8++) {
            float4 wa0 = *(const float4*)&w0[c8*8], wa1 = *(const float4*)&w0[c8*8+4];
            float4 wb0 = *(const float4*)&w1[c8*8], wb1 = *(const float4*)&w1[c8*8+4];
            float4 wc0 = *(const float4*)&w2[c8*8], wc1 = *(const float4*)&w2[c8*8+4];
            #pragma unroll
            for (int j = 0; j < 8; j++) {
                int row = rg + 64*j;
                uint4 zu = *(const uint4*)&zh[row*68 + c8*4];
                float2 f0 = __half22float2(((const __half2*)&zu)[0]);
                float2 f1 = __half22float2(((const __half2*)&zu)[1]);
                float2 f2 = __half22float2(((const __half2*)&zu)[2]);
                float2 f3 = __half22float2(((const __half2*)&zu)[3]);
                float zv[8] = {f0.x,f0.y,f1.x,f1.y,f2.x,f2.y,f3.x,f3.y};
                float wA[8] = {wa0.x,wa0.y,wa0.z,wa0.w,wa1.x,wa1.y,wa1.z,wa1.w};
                float wB[8] = {wb0.x,wb0.y,wb0.z,wb0.w,wb1.x,wb1.y,wb1.z,wb1.w};
                float wC[8] = {wc0.x,wc0.y,wc0.z,wc0.w,wc1.x,wc1.y,wc1.z,wc1.w};
                #pragma unroll
                for (int e = 0; e < 8; e++) {
                    a[j][0] += zv[e]*wA[e];
                    a[j][1] += zv[e]*wB[e];
                    a[j][2] += zv[e]*wC[e];
                    ssq[j]  += zv[e]*zv[e];
                }
            }
        }
        #pragma unroll
        for (int j=0;j<8;j++) {
            int k = rg + 64*j;
            float rs = rsqrtf(ssq[j]*(1.f/128.f) + 1e-6f);
            float cf = WLc * rs;
            L[(hg*3+0)*512 + k] += cf*a[j][0];
            L[(hg*3+1)*512 + k] += cf*a[j][1];
            L[(hg*3+2)*512 + k] += cf*a[j][2];
            if (hg == 0) rsts[k] = rs;
        }
    }
    __syncthreads();

    int warp = t >> 5, lane = t & 31;
    for (int r = warp; r < 12; r += 8) {
        float* row = &L[r*512];
        float m = -1e30f;
        #pragma unroll
        for (int i = lane; i < 512; i += 32) m = fmaxf(m, row[i]);
        #pragma unroll
        for (int o = 16; o; o >>= 1) m = fmaxf(m, __shfl_xor_sync(0xffffffffu, m, o));
        float s = 0.f;
        #pragma unroll
        for (int i = lane; i < 512; i += 32) { float v = __expf(row[i]-m); row[i] = v; s += v; }
        #pragma unroll
        for (int o = 16; o; o >>= 1) s += __shfl_xor_sync(0xffffffffu, s, o);
        float inv = 1.f/s;
        #pragma unroll
        for (int i = lane; i < 512; i += 32) row[i] *= inv;
    }
    __syncthreads();

    #pragma unroll
    for (int i = 0; i < 6; i++) {
        int lin = (i*256 + t)*4;
        int h = lin >> 9, k = lin & 511;
        *(float4*)&att[(((size_t)b*Hc + h)*Nc + q)*Nc + k] = *(float4*)&L[h*512 + k];
    }

    int cg = t & 31;
    int hg2 = (t >> 5) & 3;
    int ph = t >> 7;
    float acc[3][4];
    #pragma unroll
    for (int j=0;j<3;j++) { acc[j][0]=0;acc[j][1]=0;acc[j][2]=0;acc[j][3]=0; }

    for (int kc = 0; kc < Nc; kc += 128) {
        __syncthreads();
        #pragma unroll
        for (int i = 0; i < 6; i++) {
            int idx = i*256 + t;
            int kk = idx / 12, h = idx % 12;
            as[kk*12 + h] = L[h*512 + kc + kk] * rsts[kc + kk];
        }
        __syncthreads();
        #pragma unroll 4
        for (int kk2 = 0; kk2 < 64; kk2++) {
            int krow = kc + ph*64 + kk2;
            uint2 zu = *(const uint2*)&zh[krow*68 + cg*2];
            float2 fA = __half22float2(((const __half2*)&zu)[0]);
            float2 fB = __half22float2(((const __half2*)&zu)[1]);
            const float* ap = &as[(ph*64 + kk2)*12 + hg2*3];
            float b0 = ap[0], b1 = ap[1], b2 = ap[2];
            acc[0][0] += b0*fA.x; acc[0][1] += b0*fA.y; acc[0][2] += b0*fB.x; acc[0][3] += b0*fB.y;
            acc[1][0] += b1*fA.x; acc[1][1] += b1*fA.y; acc[1][2] += b1*fB.x; acc[1][3] += b1*fB.y;
            acc[2][0] += b2*fA.x; acc[2][1] += b2*fA.y; acc[2][2] += b2*fB.x; acc[2][3] += b2*fB.y;
        }
    }
    __syncthreads();
    if (ph == 1) {
        float* red = &ws[(t & 127)*12];
        #pragma unroll
        for (int j=0;j<3;j++)
            #pragma unroll
            for (int i=0;i<4;i++) red[j*4+i] = acc[j][i];
    }
    __syncthreads();
    if (ph == 0) {
        const float* red = &ws[t*12];
        float4 nw = *(const float4*)&nzw[cg*4];
        float nv[4] = {nw.x, nw.y, nw.z, nw.w};
        float* cc = cat + (size_t)bq*CATc + 768;
        #pragma unroll
        for (int j=0;j<3;j++) {
            int h = hg2*3 + j;
            #pragma unroll
            for (int i=0;i<4;i++)
                cc[h*CZc + cg*4 + i] = (acc[j][i] + red[j*4+i]) * nv[i];
        }
    }
}

// ---------------- AV (split-K over k): 128 thr, thread = 4q x 7c ----------------
__global__ __launch_bounds__(128) void k_av(
        const float* __restrict__ att, const float* __restrict__ proj,
        float* __restrict__ P0, float* __restrict__ P1) {
    __shared__ float As[32][68];
    __shared__ float Ws[32][57];
    int bh = blockIdx.y; int h = bh % Hc, b = bh / Hc;
    int q0 = blockIdx.x*64;
    int zh = blockIdx.z;
    float* P = zh ? P1 : P0;
    int t = threadIdx.x;
    int cg = t >> 4, qg = t & 15;
    float acc[4][7];
    #pragma unroll
    for (int i=0;i<4;i++)
        #pragma unroll
        for (int j=0;j<7;j++) acc[i][j]=0;

    int kbeg = zh*256, kend = kbeg + 256;
    for (int kc = kbeg; kc < kend; kc += 32) {
        #pragma unroll
        for (int i = 0; i < 4; i++) {
            int idx = i*128 + t;
            int q = idx >> 3, kf = idx & 7;
            float4 v = *(const float4*)&att[(((size_t)bh)*Nc + q0 + q)*Nc + kc + kf*4];
            #pragma unroll
            for (int j=0;j<4;j++) As[kf*4+j][q] = ((const float*)&v)[j];
        }
        #pragma unroll
        for (int i = 0; i < 14; i++) {
            int idx = i*128 + t;
            if (idx < 32*56) {
                int kk = idx / 56, c = idx % 56;
                int kg = kc + kk;
                float val;
                if (c < 32) val = proj[(size_t)(b*Nc + kg)*PROJc + 768 + h*32 + c];
                else        val = proj[(size_t)(b*Nc + kg)*PROJc + 1440 + h*24 + (c-32)];
                Ws[kk][c] = val;
            }
        }
        __syncthreads();
        #pragma unroll 4
        for (int kk = 0; kk < 32; kk++) {
            float4 a4 = *(const float4*)&As[kk][qg*4];
            float a[4] = {a4.x, a4.y, a4.z, a4.w};
            #pragma unroll
            for (int j=0;j<7;j++) {
                float w = Ws[kk][cg*7+j];
                acc[0][j] += a[0]*w; acc[1][j] += a[1]*w;
                acc[2][j] += a[2]*w; acc[3][j] += a[3]*w;
            }
        }
        __syncthreads();
    }
    #pragma unroll
    for (int i=0;i<4;i++) {
        int q = q0 + qg*4 + i;
        #pragma unroll
        for (int j=0;j<7;j++) {
            int c = cg*7 + j;
            P[((size_t)(b*Nc + q)*Hc + h)*56 + c] = acc[i][j];
        }
    }
}

// ---------------- AV reduce + op->local fused ----------------
__global__ void k_avred_op(const float* __restrict__ P0, const float* __restrict__ P1,
                           const float* __restrict__ rot, const float* __restrict__ trans,
                           float* __restrict__ cat) {
    int idx = blockIdx.x*blockDim.x + threadIdx.x;
    const int total_o = BNc*Hc*32;
    if (idx < total_o) {
        int c = idx & 31; int r = idx >> 5;
        int h = r % Hc; int bq = r / Hc;
        size_t pi = ((size_t)bq*Hc + h)*56 + c;
        cat[(size_t)bq*CATc + h*32 + c] = P0[pi] + P1[pi];
    } else {
        int j = idx - total_o;
        if (j >= BNc*Hc*PVc) return;
        int p = j & 7; int r = j >> 3;
        int h = r % Hc; int bq = r / Hc;
        size_t pi = ((size_t)bq*Hc + h)*56 + 32 + p*3;
        float x = P0[pi+0] + P1[pi+0];
        float y = P0[pi+1] + P1[pi+1];
        float zv = P0[pi+2] + P1[pi+2];
        const float* R = rot + (size_t)bq*9;
        const float* tr = trans + (size_t)bq*3;
        x -= tr[0]; y -= tr[1]; zv -= tr[2];
        float lx = R[0]*x + R[3]*y + R[6]*zv;
        float ly = R[1]*x + R[4]*y + R[7]*zv;
        float lz = R[2]*x + R[5]*y + R[8]*zv;
        float* cc = cat + (size_t)bq*CATc;
        cc[384 + h*24 + p*3+0] = lx;
        cc[384 + h*24 + p*3+1] = ly;
        cc[384 + h*24 + p*3+2] = lz;
        cc[672 + h*8 + p] = sqrtf(lx*lx + ly*ly + lz*lz + 1e-8f);
    }
}

__global__ void k_frame(const float* __restrict__ x, const float* __restrict__ wf,
                        const float* __restrict__ rot, const float* __restrict__ trans,
                        float* __restrict__ out_rot, float* __restrict__ out_trans) {
    int warp = (blockIdx.x*blockDim.x + threadIdx.x) >> 5;
    int lane = threadIdx.x & 31;
    if (warp >= BNc) return;
    const float* xr = x + (size_t)warp*CSc;
    float v[6];
    #pragma unroll
    for (int o = 0; o < 6; o++) {
        float d = 0.f;
        for (int c = lane; c < CSc; c += 32) d += xr[c]*wf[o*CSc + c];
        #pragma unroll
        for (int off = 16; off; off >>= 1) d += __shfl_xor_sync(0xffffffffu, d, off);
        v[o] = d;
    }
    if (lane == 0) {
        float qx = v[0], qy = v[1], qz = v[2];
        float inv = rsqrtf(1.f + qx*qx + qy*qy + qz*qz);
        float qw = inv; qx *= inv; qy *= inv; qz *= inv;
        float U[9] = {
            1-2*(qy*qy+qz*qz), 2*(qx*qy-qw*qz), 2*(qx*qz+qw*qy),
            2*(qx*qy+qw*qz), 1-2*(qx*qx+qz*qz), 2*(qy*qz-qw*qx),
            2*(qx*qz-qw*qy), 2*(qy*qz+qw*qx), 1-2*(qx*qx+qy*qy)};
        const float* R = rot + (size_t)warp*9;
        float* Ro = out_rot + (size_t)warp*9;
        #pragma unroll
        for (int i = 0; i < 3; i++)
            #pragma unroll
            for (int j = 0; j < 3; j++)
                Ro[i*3+j] = R[i*3+0]*U[0*3+j] + R[i*3+1]*U[1*3+j] + R[i*3+2]*U[2*3+j];
        const float* t = trans + (size_t)warp*3;
        float* To = out_trans + (size_t)warp*3;
        #pragma unroll
        for (int i = 0; i < 3; i++)
            To[i] = R[i*3+0]*v[3] + R[i*3+1]*v[4] + R[i*3+2]*v[5] + t[i];
    }
}

// ---------------- launch ----------------
static float* sym(const void* s) {
    void* p = nullptr;
    cudaGetSymbolAddress(&p, s);
    return (float*)p;
}

extern "C" void kernel_launch(void* const* d_in, const int* in_sizes, int n_in,
                              void* d_out, int out_size) {
    (void)in_sizes; (void)n_in; (void)out_size;
    const float* in_s    = (const float*)d_in[0];
    const float* rot     = (const float*)d_in[1];
    const float* trans   = (const float*)d_in[2];
    const float* z       = (const float*)d_in[3];
    const float* norm_z_w = (const float*)d_in[5];
    const float* norm1_w  = (const float*)d_in[6];
    const float* norm2_w  = (const float*)d_in[7];
    const float* norm3_w  = (const float*)d_in[8];
    const float* w_qkv    = (const float*)d_in[9];
    const float* w_qpts   = (const float*)d_in[10];
    const float* w_kpts   = (const float*)d_in[11];
    const float* w_vpts   = (const float*)d_in[12];
    const float* head_w   = (const float*)d_in[13];
    const float* w_pair   = (const float*)d_in[14];
    const float* w_out    = (const float*)d_in[15];
    const float* w12      = (const float*)d_in[16];
    const float* w3       = (const float*)d_in[17];
    const float* w_frame  = (const float*)d_in[18];

    float* out       = (float*)d_out;
    float* out_s     = out;
    float* out_rot   = out + BNc*CSc;
    float* out_trans = out + BNc*CSc + BNc*9;

    float* s0   = sym(g_s0);
    float* proj = sym(g_proj);
    float* qn   = sym(g_qn);
    float* kn   = sym(g_kn);
    float* att  = sym(g_att);
    float* cat  = sym(g_cat);
    float* x    = sym(g_x);
    float* hs   = sym(g_hs);
    float* p0   = sym(g_p0);
    float* p1   = sym(g_p1);
    float* p2   = sym(g_p2);
    float* avp0 = sym(g_avp0);
    float* avp1 = sym(g_avp1);

    cudaFuncSetAttribute(k_zfuse, cudaFuncAttributeMaxDynamicSharedMemorySize, ZF_SMEM);

    k_rmsnorm<<<BNc/8, 256>>>(in_s, norm1_w, s0, BNc, CSc);

    k_proj<<<dim3(PROJc/64, BNc/128), 256>>>(s0, w_qkv, w_qpts, w_kpts, w_vpts, proj);

    k_ropepoints<<<(BNc*Hc*16)/256, 256>>>(proj, rot, trans, qn, kn);

    k_logits<<<dim3(Nc/64, Nc/64, Bc*Hc), 256>>>(proj, qn, kn, head_w, att);

    k_zfuse<<<BNc, 256, ZF_SMEM>>>(att, z, norm_z_w, w_pair, cat);

    k_av<<<dim3(Nc/64, Bc*Hc, 2), 128>>>(att, proj, avp0, avp1);
    k_avred_op<<<(BNc*Hc*40 + 255)/256, 256>>>(avp0, avp1, rot, trans, cat);

    k_gemmK<<<dim3(CSc/64, BNc/128, 3), 256>>>(cat, w_out, p0, p1, p2, CSc, CATc, 768);
    k_red3norm<<<BNc/8, 256>>>(in_s, p0, p1, p2, norm2_w, out_s, x);

    k_glu<<<dim3(HIDc/64, BNc/128), 256>>>(x, w12, hs, CSc);

    k_gemmK<<<dim3(CSc/64, BNc/128, 3), 256>>>(hs, w3, p0, p1, p2, CSc, HIDc, 512);
    k_red3norm<<<BNc/8, 256>>>(out_s, p0, p1, p2, norm3_w, out_s, x);

    k_frame<<<BNc/8, 256>>>(x, w_frame, rot, trans, out_rot, out_trans);
}